// round 12
// baseline (speedup 1.0000x reference)
#include <cuda_runtime.h>
#include <math.h>
#include <stdint.h>

#define Bb   2
#define Tt   2048
#define DIMc 1024
#define NHh  16
#define HDd  64
#define NTOK (Bb*Tt)

// Scratch (device globals — no runtime allocation allowed)
__device__ float g_qkv[(size_t)NTOK * 3 * DIMc];     // [tok][3*DIM]  q|k|v
__device__ float g_y[(size_t)NTOK * DIMc];           // attention output [tok][DIM]
__device__ float g_ah[(size_t)NTOK * DIMc];          // activation hi (x, then y)
__device__ float g_al[(size_t)NTOK * DIMc];          // activation lo
__device__ float g_wqh[(size_t)3 * DIMc * DIMc];     // W_qkv^T hi [3*DIM][DIM]
__device__ float g_wql[(size_t)3 * DIMc * DIMc];     // W_qkv^T lo
__device__ float g_wph[(size_t)DIMc * DIMc];         // W_proj^T hi
__device__ float g_wpl[(size_t)DIMc * DIMc];         // W_proj^T lo

// ===========================================================================
// Helpers
// ===========================================================================
__device__ __forceinline__ uint32_t smem_u32(const void* p) {
    uint32_t a;
    asm("{ .reg .u64 t; cvta.to.shared.u64 t, %1; cvt.u32.u64 %0, t; }" : "=r"(a) : "l"(p));
    return a;
}
__device__ __forceinline__ void cp_async16(uint32_t dst, const void* src) {
    asm volatile("cp.async.cg.shared.global [%0], [%1], 16;" :: "r"(dst), "l"(src));
}
#define CP_COMMIT()  asm volatile("cp.async.commit_group;")
#define CP_WAIT1()   asm volatile("cp.async.wait_group 1;" ::: "memory")
#define CP_WAIT0()   asm volatile("cp.async.wait_group 0;" ::: "memory")

// Round f32 -> tf32 (round-to-nearest into 10-bit mantissa, result is f32 bits)
__device__ __forceinline__ float f2tf32f(float f) {
    uint32_t r;
    asm("cvt.rna.tf32.f32 %0, %1;" : "=r"(r) : "f"(f));
    return __uint_as_float(r);
}

// tf32 mma: D = A(16x8, row) * B(8x8, col) + D
__device__ __forceinline__ void mma_tf32(float* d, const uint32_t* a, const uint32_t* b) {
    asm volatile(
        "mma.sync.aligned.m16n8k8.row.col.f32.tf32.tf32.f32 "
        "{%0,%1,%2,%3}, {%4,%5,%6,%7}, {%8,%9}, {%0,%1,%2,%3};"
        : "+f"(d[0]), "+f"(d[1]), "+f"(d[2]), "+f"(d[3])
        : "r"(a[0]), "r"(a[1]), "r"(a[2]), "r"(a[3]), "r"(b[0]), "r"(b[1]));
}

// ldmatrix x4: four 8x8 b16 matrices == four 8x4 b32 blocks in fragment layout
__device__ __forceinline__ void ldsm_x4(uint32_t* r, uint32_t addr) {
    asm volatile("ldmatrix.sync.aligned.m8n8.x4.shared.b16 {%0,%1,%2,%3}, [%4];"
        : "=r"(r[0]), "=r"(r[1]), "=r"(r[2]), "=r"(r[3]) : "r"(addr));
}

// ===========================================================================
// Elementwise hi/lo split (for activations)
// ===========================================================================
__global__ __launch_bounds__(256) void split_hi_lo(
    const float* __restrict__ X, float* __restrict__ H, float* __restrict__ L)
{
    const int i = blockIdx.x * 256 + threadIdx.x;
    float4 v = ((const float4*)X)[i];
    float4 h, l;
    h.x = f2tf32f(v.x); l.x = f2tf32f(v.x - h.x);
    h.y = f2tf32f(v.y); l.y = f2tf32f(v.y - h.y);
    h.z = f2tf32f(v.z); l.z = f2tf32f(v.z - h.z);
    h.w = f2tf32f(v.w); l.w = f2tf32f(v.w - h.w);
    ((float4*)H)[i] = h;
    ((float4*)L)[i] = l;
}

// ===========================================================================
// Weight transpose + split: Wh/Wl[n][k] = split(W[k][n])
// ===========================================================================
__global__ __launch_bounds__(256) void transpose_split(
    const float* __restrict__ W, float* __restrict__ Wh, float* __restrict__ Wl,
    int K, int N)
{
    __shared__ float t[32][33];
    const int n0 = blockIdx.x * 32, k0 = blockIdx.y * 32;
    const int x = threadIdx.x, y = threadIdx.y;
    #pragma unroll
    for (int i = y; i < 32; i += 8)
        t[i][x] = W[(size_t)(k0 + i) * N + n0 + x];
    __syncthreads();
    #pragma unroll
    for (int i = y; i < 32; i += 8) {
        const float v = t[x][i];
        const float h = f2tf32f(v);
        Wh[(size_t)(n0 + i) * K + k0 + x] = h;
        Wl[(size_t)(n0 + i) * K + k0 + x] = f2tf32f(v - h);
    }
}

// ===========================================================================
// 3xTF32 GEMM, pre-split operands, ldmatrix fragment loads.
// C[M,N] = A[M,K] * Bt[N,K]^T at ~fp32 accuracy.
// CTA tile 128x128, BK=32, 8 warps (2m x 4n), warp tile 64x32.
// Smem per tile (crosswise-4): elem(m,k) at (k/4)*512 + m*4 + (k%4) floats.
// Stage layout: [Ah 4096][Al 4096][Bh 4096][Bl 4096] floats; 2 stages = 128 KB.
// ===========================================================================
#define GEMM_SMEM (2 * 16384 * 4)

__global__ __launch_bounds__(256) void gemm_mma3(
    const float* __restrict__ Ah, const float* __restrict__ Al,
    const float* __restrict__ Bh, const float* __restrict__ Bl,
    float* __restrict__ C, int M, int N, int K)
{
    extern __shared__ float sm[];

    const int tid  = threadIdx.x;
    const int lane = tid & 31;
    const int wid  = tid >> 5;
    const int wm   = wid >> 2;         // 0..1  (64-row slab)
    const int wn   = wid & 3;          // 0..3  (32-col slab)
    const int r    = lane >> 2;        // 0..7
    const int c    = lane & 3;         // 0..3
    const int lane8 = lane & 7, mat = lane >> 3;
    const int m0 = blockIdx.y * 128, n0 = blockIdx.x * 128;
    const int NK = K >> 5;

    // Per-thread ldmatrix base offsets (floats):
    //   matrices 0/1: rows (mat&1)*8 + lane8 (two 8-row blocks), k-group 0
    //   matrices 2/3: same rows, k-group 1 (+512 floats)
    const uint32_t a_off = (uint32_t)((mat >> 1) * 512 + (wm * 64 + (mat & 1) * 8 + lane8) * 4);
    const uint32_t b_off = (uint32_t)((mat >> 1) * 512 + (wn * 32 + (mat & 1) * 8 + lane8) * 4);

    float acc[4][4][4] = {};           // [m-tile][n-tile][c-regs]

    auto load_stage = [&](int kt, int s) {
        const int k0 = kt * 32;
        float* st = sm + s * 16384;
        #pragma unroll
        for (int i = 0; i < 4; i++) {
            const int idx = tid + i * 256;     // 0..1023
            const int m = idx >> 3, q = idx & 7;
            const uint32_t soff = (uint32_t)(q * 512 + m * 4);
            const size_t ga = (size_t)(m0 + m) * K + k0 + q * 4;
            const size_t gb = (size_t)(n0 + m) * K + k0 + q * 4;
            cp_async16(smem_u32(st + soff),          Ah + ga);
            cp_async16(smem_u32(st + 4096 + soff),   Al + ga);
            cp_async16(smem_u32(st + 8192 + soff),   Bh + gb);
            cp_async16(smem_u32(st + 12288 + soff),  Bl + gb);
        }
    };

    load_stage(0, 0);
    CP_COMMIT();

    for (int kt = 0; kt < NK; kt++) {
        const int s = kt & 1;
        if (kt + 1 < NK) {
            load_stage(kt + 1, s ^ 1);
            CP_COMMIT();
            CP_WAIT1();
        } else {
            CP_WAIT0();
        }
        __syncthreads();

        const float* st = sm + s * 16384;
        const uint32_t aH = smem_u32(st) + a_off * 4;
        const uint32_t aL = aH + 4096 * 4;
        const uint32_t bH = smem_u32(st) + 8192 * 4 + b_off * 4;
        const uint32_t bL = bH + 4096 * 4;

        #pragma unroll
        for (int ks = 0; ks < 4; ks++) {       // k = 8*ks .. 8*ks+7
            uint32_t ahi[4][4], alo[4][4], bhi[4][2], blo[4][2];
            #pragma unroll
            for (int i = 0; i < 4; i++) {
                ldsm_x4(ahi[i], aH + (uint32_t)((ks * 1024 + i * 64) * 4));
                ldsm_x4(alo[i], aL + (uint32_t)((ks * 1024 + i * 64) * 4));
            }
            #pragma unroll
            for (int jp = 0; jp < 2; jp++) {
                // j-tile pair stride: 16 n-rows = 64 floats (NOT 128 — R10 bug)
                uint32_t th[4], tl[4];
                ldsm_x4(th, bH + (uint32_t)((ks * 1024 + jp * 64) * 4));
                ldsm_x4(tl, bL + (uint32_t)((ks * 1024 + jp * 64) * 4));
                bhi[2 * jp][0] = th[0]; bhi[2 * jp + 1][0] = th[1];
                bhi[2 * jp][1] = th[2]; bhi[2 * jp + 1][1] = th[3];
                blo[2 * jp][0] = tl[0]; blo[2 * jp + 1][0] = tl[1];
                blo[2 * jp][1] = tl[2]; blo[2 * jp + 1][1] = tl[3];
            }
            #pragma unroll
            for (int i = 0; i < 4; i++)
                #pragma unroll
                for (int j = 0; j < 4; j++) {
                    mma_tf32(acc[i][j], alo[i], bhi[j]);
                    mma_tf32(acc[i][j], ahi[i], blo[j]);
                    mma_tf32(acc[i][j], ahi[i], bhi[j]);
                }
        }
        __syncthreads();
    }

    // Epilogue: c0,c1 -> (row, 2c..2c+1); c2,c3 -> (row+8, ...)
    #pragma unroll
    for (int i = 0; i < 4; i++) {
        const int row = m0 + wm * 64 + i * 16 + r;
        #pragma unroll
        for (int j = 0; j < 4; j++) {
            const int col = n0 + wn * 32 + j * 8 + 2 * c;
            *(float2*)&C[(size_t)row * N + col] =
                make_float2(acc[i][j][0], acc[i][j][1]);
            *(float2*)&C[(size_t)(row + 8) * N + col] =
                make_float2(acc[i][j][2], acc[i][j][3]);
        }
    }
}

// ===========================================================================
// RoPE (in place on q, k segments of g_qkv)
// ===========================================================================
__global__ __launch_bounds__(1024) void rope_kernel(
    const float* __restrict__ sin_, const float* __restrict__ cos_)
{
    const int tok = blockIdx.x;
    const int t = tok & (Tt - 1);
    const int j = threadIdx.x;
    const int seg = j >> 9;
    const int p = j & 511;
    float* base = g_qkv + (size_t)tok * 3 * DIMc + seg * DIMc;
    const int d = p * 2;
    const int dh = d & (HDd - 1);
    const float c = cos_[t * HDd + dh];
    const float s = sin_[t * HDd + dh];
    float2 v = *(float2*)&base[d];
    float2 r = make_float2(v.x * c - v.y * s, v.y * c + v.x * s);
    *(float2*)&base[d] = r;
}

// ===========================================================================
// Flash attention, fp32, causal. BQ=BKV=64, 256 threads, 4x4 per thread.
// ===========================================================================
#define FLASH_SMEM ((3 * 64 * 64 + 3 * 64) * 4)

__global__ __launch_bounds__(256) void flash_kernel(float* __restrict__ Y)
{
    extern __shared__ float fsm[];
    float* Qs    = fsm;
    float* KS    = fsm + 4096;
    float* Vs    = fsm + 8192;
    float* row_m = fsm + 12288;
    float* row_l = row_m + 64;
    float* row_c = row_l + 64;

    const int qt = blockIdx.x;
    const int h  = blockIdx.y;
    const int b  = blockIdx.z;
    const int tid = threadIdx.x;
    const int tr = tid >> 4;
    const int tc = tid & 15;
    const int lrow = tid >> 2, llane = tid & 3;

    const int tok0 = b * Tt + qt * 64;
    const float* qbase = g_qkv + (size_t)tok0 * 3 * DIMc + h * HDd;

    #pragma unroll
    for (int cc = 0; cc < 4; cc++) {
        const int col = cc * 16 + llane * 4;
        float4 v = *(const float4*)(qbase + (size_t)lrow * 3 * DIMc + col);
        v.x *= 0.125f; v.y *= 0.125f; v.z *= 0.125f; v.w *= 0.125f;
        *(float4*)&Qs[lrow * 64 + col] = v;
    }
    if (tid < 64) { row_m[tid] = -INFINITY; row_l[tid] = 0.0f; }

    float o[4][4] = {};

    for (int kt = 0; kt <= qt; kt++) {
        const int ktok0 = b * Tt + kt * 64;
        const float* kbase = g_qkv + (size_t)ktok0 * 3 * DIMc + DIMc + h * HDd;
        const float* vbase = kbase + DIMc;

        __syncthreads();

        #pragma unroll
        for (int cc = 0; cc < 4; cc++) {
            const int col = cc * 16 + llane * 4;
            float4 kv4 = *(const float4*)(kbase + (size_t)lrow * 3 * DIMc + col);
            KS[(col + 0) * 64 + lrow] = kv4.x;
            KS[(col + 1) * 64 + lrow] = kv4.y;
            KS[(col + 2) * 64 + lrow] = kv4.z;
            KS[(col + 3) * 64 + lrow] = kv4.w;
            float4 vv = *(const float4*)(vbase + (size_t)lrow * 3 * DIMc + col);
            *(float4*)&Vs[lrow * 64 + col] = vv;
        }
        __syncthreads();

        // S = Q * K^T
        float s_[4][4] = {};
        #pragma unroll
        for (int d0 = 0; d0 < 64; d0 += 4) {
            float a[4][4], bk[4][4];
            #pragma unroll
            for (int i = 0; i < 4; i++) {
                float4 t = *(const float4*)&Qs[(tr * 4 + i) * 64 + d0];
                a[i][0] = t.x; a[i][1] = t.y; a[i][2] = t.z; a[i][3] = t.w;
            }
            #pragma unroll
            for (int dd = 0; dd < 4; dd++) {
                float4 t = *(const float4*)&KS[(d0 + dd) * 64 + tc * 4];
                bk[dd][0] = t.x; bk[dd][1] = t.y; bk[dd][2] = t.z; bk[dd][3] = t.w;
            }
            #pragma unroll
            for (int i = 0; i < 4; i++)
                #pragma unroll
                for (int j = 0; j < 4; j++)
                    s_[i][j] += a[i][0] * bk[0][j] + a[i][1] * bk[1][j]
                              + a[i][2] * bk[2][j] + a[i][3] * bk[3][j];
        }

        if (kt == qt) {
            #pragma unroll
            for (int i = 0; i < 4; i++)
                #pragma unroll
                for (int j = 0; j < 4; j++)
                    if ((tc * 4 + j) > (tr * 4 + i)) s_[i][j] = -INFINITY;
        }

        __syncthreads();

        #pragma unroll
        for (int i = 0; i < 4; i++) {
            float4 st = make_float4(s_[i][0], s_[i][1], s_[i][2], s_[i][3]);
            *(float4*)&KS[(tr * 4 + i) * 64 + tc * 4] = st;
        }
        __syncthreads();

        // Parallel online softmax: 4 threads per row (quarter-row each)
        {
            const int q = tid >> 2;
            const int quad = tid & 3;
            float* row = &KS[q * 64 + quad * 16];
            const float m_old = row_m[q];
            float4 v0 = *(float4*)(row + 0);
            float4 v1 = *(float4*)(row + 4);
            float4 v2 = *(float4*)(row + 8);
            float4 v3 = *(float4*)(row + 12);
            float mx = fmaxf(fmaxf(fmaxf(v0.x, v0.y), fmaxf(v0.z, v0.w)),
                             fmaxf(fmaxf(v1.x, v1.y), fmaxf(v1.z, v1.w)));
            mx = fmaxf(mx, fmaxf(fmaxf(fmaxf(v2.x, v2.y), fmaxf(v2.z, v2.w)),
                                 fmaxf(fmaxf(v3.x, v3.y), fmaxf(v3.z, v3.w))));
            mx = fmaxf(mx, __shfl_xor_sync(0xffffffffu, mx, 1));
            mx = fmaxf(mx, __shfl_xor_sync(0xffffffffu, mx, 2));
            mx = fmaxf(mx, m_old);
            v0.x = __expf(v0.x - mx); v0.y = __expf(v0.y - mx);
            v0.z = __expf(v0.z - mx); v0.w = __expf(v0.w - mx);
            v1.x = __expf(v1.x - mx); v1.y = __expf(v1.y - mx);
            v1.z = __expf(v1.z - mx); v1.w = __expf(v1.w - mx);
            v2.x = __expf(v2.x - mx); v2.y = __expf(v2.y - mx);
            v2.z = __expf(v2.z - mx); v2.w = __expf(v2.w - mx);
            v3.x = __expf(v3.x - mx); v3.y = __expf(v3.y - mx);
            v3.z = __expf(v3.z - mx); v3.w = __expf(v3.w - mx);
            float l = (v0.x + v0.y + v0.z + v0.w) + (v1.x + v1.y + v1.z + v1.w)
                    + (v2.x + v2.y + v2.z + v2.w) + (v3.x + v3.y + v3.z + v3.w);
            *(float4*)(row + 0)  = v0;
            *(float4*)(row + 4)  = v1;
            *(float4*)(row + 8)  = v2;
            *(float4*)(row + 12) = v3;
            l += __shfl_xor_sync(0xffffffffu, l, 1);
            l += __shfl_xor_sync(0xffffffffu, l, 2);
            if (quad == 0) {
                const float corr = __expf(m_old - mx);
                row_m[q] = mx;
                row_l[q] = row_l[q] * corr + l;
                row_c[q] = corr;
            }
        }
        __syncthreads();

        // Rescale O, accumulate O += P * V
        float ci[4];
        #pragma unroll
        for (int i = 0; i < 4; i++) ci[i] = row_c[tr * 4 + i];
        #pragma unroll
        for (int i = 0; i < 4; i++)
            #pragma unroll
            for (int j = 0; j < 4; j++) o[i][j] *= ci[i];

        #pragma unroll
        for (int kv0 = 0; kv0 < 64; kv0 += 4) {
            float p[4][4], v4[4][4];
            #pragma unroll
            for (int i = 0; i < 4; i++) {
                float4 t = *(const float4*)&KS[(tr * 4 + i) * 64 + kv0];
                p[i][0] = t.x; p[i][1] = t.y; p[i][2] = t.z; p[i][3] = t.w;
            }
            #pragma unroll
            for (int kk = 0; kk < 4; kk++) {
                float4 t = *(const float4*)&Vs[(kv0 + kk) * 64 + tc * 4];
                v4[kk][0] = t.x; v4[kk][1] = t.y; v4[kk][2] = t.z; v4[kk][3] = t.w;
            }
            #pragma unroll
            for (int i = 0; i < 4; i++)
                #pragma unroll
                for (int j = 0; j < 4; j++)
                    o[i][j] += p[i][0] * v4[0][j] + p[i][1] * v4[1][j]
                             + p[i][2] * v4[2][j] + p[i][3] * v4[3][j];
        }
    }

    #pragma unroll
    for (int i = 0; i < 4; i++) {
        const float li = 1.0f / row_l[tr * 4 + i];
        float4 st = make_float4(o[i][0] * li, o[i][1] * li, o[i][2] * li, o[i][3] * li);
        *(float4*)&Y[(size_t)(tok0 + tr * 4 + i) * DIMc + h * HDd + tc * 4] = st;
    }
}

// ===========================================================================
extern "C" void kernel_launch(void* const* d_in, const int* in_sizes, int n_in,
                              void* d_out, int out_size)
{
    const float* x      = (const float*)d_in[0];
    const float* sin_   = (const float*)d_in[1];
    const float* cos_   = (const float*)d_in[2];
    const float* W_qkv  = (const float*)d_in[3];
    const float* W_proj = (const float*)d_in[4];
    float* out = (float*)d_out;

    void *pqkv = nullptr, *py = nullptr, *pah = nullptr, *pal = nullptr;
    void *pwqh = nullptr, *pwql = nullptr, *pwph = nullptr, *pwpl = nullptr;
    cudaGetSymbolAddress(&pqkv, g_qkv);
    cudaGetSymbolAddress(&py, g_y);
    cudaGetSymbolAddress(&pah, g_ah);
    cudaGetSymbolAddress(&pal, g_al);
    cudaGetSymbolAddress(&pwqh, g_wqh);
    cudaGetSymbolAddress(&pwql, g_wql);
    cudaGetSymbolAddress(&pwph, g_wph);
    cudaGetSymbolAddress(&pwpl, g_wpl);

    cudaFuncSetAttribute(gemm_mma3, cudaFuncAttributeMaxDynamicSharedMemorySize, GEMM_SMEM);
    cudaFuncSetAttribute(flash_kernel, cudaFuncAttributeMaxDynamicSharedMemorySize, FLASH_SMEM);

    const int nsplit = NTOK * DIMc / 4 / 256;   // float4s per thread-block grid

    // 0) Split weights (transposed) and x into tf32 hi/lo
    transpose_split<<<dim3(3 * DIMc / 32, DIMc / 32), dim3(32, 8)>>>(
        W_qkv, (float*)pwqh, (float*)pwql, DIMc, 3 * DIMc);
    transpose_split<<<dim3(DIMc / 32, DIMc / 32), dim3(32, 8)>>>(
        W_proj, (float*)pwph, (float*)pwpl, DIMc, DIMc);
    split_hi_lo<<<nsplit, 256>>>(x, (float*)pah, (float*)pal);

    // 1) QKV = x @ W_qkv  (3xTF32, pre-split, ldmatrix)
    gemm_mma3<<<dim3(3 * DIMc / 128, NTOK / 128), 256, GEMM_SMEM>>>(
        (const float*)pah, (const float*)pal, (const float*)pwqh, (const float*)pwql,
        (float*)pqkv, NTOK, 3 * DIMc, DIMc);

    // 2) RoPE on q, k
    rope_kernel<<<NTOK, 1024>>>(sin_, cos_);

    // 3) Causal flash attention -> g_y
    flash_kernel<<<dim3(Tt / 64, NHh, Bb), 256, FLASH_SMEM>>>((float*)py);

    // 4) Split y, then out = y @ W_proj
    split_hi_lo<<<nsplit, 256>>>((const float*)py, (float*)pah, (float*)pal);
    gemm_mma3<<<dim3(DIMc / 128, NTOK / 128), 256, GEMM_SMEM>>>(
        (const float*)pah, (const float*)pal, (const float*)pwph, (const float*)pwpl,
        out, NTOK, DIMc, DIMc);
}

// round 15
// speedup vs baseline: 1.5680x; 1.5680x over previous
#include <cuda_runtime.h>
#include <cuda_fp16.h>
#include <math.h>
#include <stdint.h>

#define Bb   2
#define Tt   2048
#define DIMc 1024
#define NHh  16
#define HDd  64
#define NTOK (Bb*Tt)

// Scratch (device globals — no runtime allocation allowed)
__device__ float  g_qkv[(size_t)NTOK * 3 * DIMc];    // [tok][3*DIM]  q|k|v
__device__ float  g_y[(size_t)NTOK * DIMc];          // attention output
__device__ __half g_ah[(size_t)NTOK * DIMc];         // activation hi (x, then y)
__device__ __half g_al[(size_t)NTOK * DIMc];         // activation lo
__device__ __half g_wqh[(size_t)3 * DIMc * DIMc];    // W_qkv^T hi [3*DIM][DIM]
__device__ __half g_wql[(size_t)3 * DIMc * DIMc];    // W_qkv^T lo
__device__ __half g_wph[(size_t)DIMc * DIMc];        // W_proj^T hi
__device__ __half g_wpl[(size_t)DIMc * DIMc];        // W_proj^T lo

// ===========================================================================
// Helpers
// ===========================================================================
__device__ __forceinline__ uint32_t smem_u32(const void* p) {
    uint32_t a;
    asm("{ .reg .u64 t; cvta.to.shared.u64 t, %1; cvt.u32.u64 %0, t; }" : "=r"(a) : "l"(p));
    return a;
}
__device__ __forceinline__ void cp_async16(uint32_t dst, const void* src) {
    asm volatile("cp.async.cg.shared.global [%0], [%1], 16;" :: "r"(dst), "l"(src));
}
#define CP_COMMIT()  asm volatile("cp.async.commit_group;")
#define CP_WAIT2()   asm volatile("cp.async.wait_group 2;" ::: "memory")
#define CP_WAIT1()   asm volatile("cp.async.wait_group 1;" ::: "memory")
#define CP_WAIT0()   asm volatile("cp.async.wait_group 0;" ::: "memory")

// fp16 mma k16: D(f32) = A(16x16 f16, row) * B(16x8 f16, col) + D
__device__ __forceinline__ void mma_f16(float* d, const uint32_t* a, const uint32_t* b) {
    asm volatile(
        "mma.sync.aligned.m16n8k16.row.col.f32.f16.f16.f32 "
        "{%0,%1,%2,%3}, {%4,%5,%6,%7}, {%8,%9}, {%0,%1,%2,%3};"
        : "+f"(d[0]), "+f"(d[1]), "+f"(d[2]), "+f"(d[3])
        : "r"(a[0]), "r"(a[1]), "r"(a[2]), "r"(a[3]), "r"(b[0]), "r"(b[1]));
}

__device__ __forceinline__ void ldsm_x4(uint32_t* r, uint32_t addr) {
    asm volatile("ldmatrix.sync.aligned.m8n8.x4.shared.b16 {%0,%1,%2,%3}, [%4];"
        : "=r"(r[0]), "=r"(r[1]), "=r"(r[2]), "=r"(r[3]) : "r"(addr));
}

// ===========================================================================
// Elementwise fp16 hi/lo split (activations): 8 floats -> 8+8 halfs per thread
// ===========================================================================
__global__ __launch_bounds__(256) void split_hi_lo(
    const float* __restrict__ X, __half* __restrict__ H, __half* __restrict__ L)
{
    const int i = blockIdx.x * 256 + threadIdx.x;   // 8-float group
    const float4 v0 = ((const float4*)X)[2 * i];
    const float4 v1 = ((const float4*)X)[2 * i + 1];
    float v[8] = {v0.x, v0.y, v0.z, v0.w, v1.x, v1.y, v1.z, v1.w};
    __half h[8], l[8];
    #pragma unroll
    for (int j = 0; j < 8; j++) {
        h[j] = __float2half_rn(v[j]);
        l[j] = __float2half_rn(v[j] - __half2float(h[j]));
    }
    ((uint4*)H)[i] = *(uint4*)h;
    ((uint4*)L)[i] = *(uint4*)l;
}

// ===========================================================================
// Weight transpose + fp16 split: Wh/Wl[n][k] = split(W[k][n])
// ===========================================================================
__global__ __launch_bounds__(256) void transpose_split(
    const float* __restrict__ W, __half* __restrict__ Wh, __half* __restrict__ Wl,
    int K, int N)
{
    __shared__ float t[32][33];
    const int n0 = blockIdx.x * 32, k0 = blockIdx.y * 32;
    const int x = threadIdx.x, y = threadIdx.y;
    #pragma unroll
    for (int i = y; i < 32; i += 8)
        t[i][x] = W[(size_t)(k0 + i) * N + n0 + x];
    __syncthreads();
    #pragma unroll
    for (int i = y; i < 32; i += 8) {
        const float v = t[x][i];
        const __half h = __float2half_rn(v);
        Wh[(size_t)(n0 + i) * K + k0 + x] = h;
        Wl[(size_t)(n0 + i) * K + k0 + x] = __float2half_rn(v - __half2float(h));
    }
}

// ===========================================================================
// 3xFP16 GEMM: C[M,N] = A[M,K] * Bt[N,K]^T at ~fp32 accuracy.
// CTA 128x128, BK=32, 8 warps (2m x 4n), warp tile 64x32, mma.m16n8k16.
// Smem stage (32 KB): [Ah 8K][Al 8K][Bh 8K][Bl 8K], each as 4 k8-slabs:
//   elem(row, k) at slab (k/8)*2048B + row*16B + (k%8)*2B  -> every ldmatrix
//   row is a distinct 16B line; conflict-free. 3 stages = 96 KB -> 2 CTA/SM.
// ===========================================================================
#define GEMM_SMEM (3 * 32768)

__global__ __launch_bounds__(256, 2) void gemm_f16x3(
    const __half* __restrict__ Ah, const __half* __restrict__ Al,
    const __half* __restrict__ Bh, const __half* __restrict__ Bl,
    float* __restrict__ C, int M, int N, int K)
{
    extern __shared__ char sm[];
    const uint32_t smem_base = smem_u32(sm);

    const int tid  = threadIdx.x;
    const int lane = tid & 31;
    const int wid  = tid >> 5;
    const int wm   = wid >> 2;         // 0..1
    const int wn   = wid & 3;          // 0..3
    const int r    = lane >> 2;        // 0..7
    const int c    = lane & 3;         // 0..3
    const int lane8 = lane & 7, mat = lane >> 3;
    const int m0 = blockIdx.y * 128, n0 = blockIdx.x * 128;
    const int NK = K >> 5;

    // ldmatrix per-lane offsets (bytes within an operand region):
    //   kg-slab select (mat>>1)*2048, row (base + (mat&1)*8 + lane8)*16
    const uint32_t a_lane_off = (uint32_t)((mat >> 1) * 2048 + (wm * 64 + (mat & 1) * 8 + lane8) * 16);
    const uint32_t b_lane_off = (uint32_t)((mat >> 1) * 2048 + (wn * 32 + (mat & 1) * 8 + lane8) * 16);

    float acc[4][4][4] = {};

    auto load_stage = [&](int kt, int s) {
        const int k0 = kt * 32;
        const uint32_t st = smem_base + (uint32_t)s * 32768;
        #pragma unroll
        for (int i = 0; i < 8; i++) {
            const int chunk = tid + i * 256;       // 0..2047
            const int region = chunk >> 9;         // 0:Ah 1:Al 2:Bh 3:Bl
            const int within = chunk & 511;
            const int row = within >> 2, kg = within & 3;
            const uint32_t dst = st + (uint32_t)(region * 8192 + kg * 2048 + row * 16);
            const __half* src;
            if      (region == 0) src = Ah + (size_t)(m0 + row) * K + k0 + kg * 8;
            else if (region == 1) src = Al + (size_t)(m0 + row) * K + k0 + kg * 8;
            else if (region == 2) src = Bh + (size_t)(n0 + row) * K + k0 + kg * 8;
            else                  src = Bl + (size_t)(n0 + row) * K + k0 + kg * 8;
            cp_async16(dst, src);
        }
    };

    load_stage(0, 0); CP_COMMIT();
    load_stage(1, 1); CP_COMMIT();

    for (int kt = 0; kt < NK; kt++) {
        const int s = kt - (kt / 3) * 3;           // kt % 3
        if (kt + 2 < NK) {
            const int s2 = (kt + 2) - ((kt + 2) / 3) * 3;
            load_stage(kt + 2, s2);
            CP_COMMIT();
            CP_WAIT2();
        } else if (kt + 1 < NK) {
            CP_WAIT1();
        } else {
            CP_WAIT0();
        }
        __syncthreads();

        const uint32_t st = smem_base + (uint32_t)s * 32768;
        const uint32_t aBase = st + a_lane_off;            // Ah region at +0
        const uint32_t bBase = st + 16384 + b_lane_off;    // Bh region

        #pragma unroll
        for (int s16 = 0; s16 < 2; s16++) {        // two k16 steps per BK=32
            uint32_t ahi[4][4], alo[4][4], bhi[4][2], blo[4][2];
            #pragma unroll
            for (int i = 0; i < 4; i++) {
                ldsm_x4(ahi[i], aBase +        (uint32_t)(s16 * 4096 + i * 256));
                ldsm_x4(alo[i], aBase + 8192 + (uint32_t)(s16 * 4096 + i * 256));
            }
            #pragma unroll
            for (int jp = 0; jp < 2; jp++) {
                uint32_t th[4], tl[4];
                ldsm_x4(th, bBase +        (uint32_t)(s16 * 4096 + jp * 256));
                ldsm_x4(tl, bBase + 8192 + (uint32_t)(s16 * 4096 + jp * 256));
                bhi[2 * jp][0] = th[0]; bhi[2 * jp + 1][0] = th[1];
                bhi[2 * jp][1] = th[2]; bhi[2 * jp + 1][1] = th[3];
                blo[2 * jp][0] = tl[0]; blo[2 * jp + 1][0] = tl[1];
                blo[2 * jp][1] = tl[2]; blo[2 * jp + 1][1] = tl[3];
            }
            #pragma unroll
            for (int i = 0; i < 4; i++)
                #pragma unroll
                for (int j = 0; j < 4; j++) {
                    mma_f16(acc[i][j], alo[i], bhi[j]);
                    mma_f16(acc[i][j], ahi[i], blo[j]);
                    mma_f16(acc[i][j], ahi[i], bhi[j]);
                }
        }
        __syncthreads();
    }

    #pragma unroll
    for (int i = 0; i < 4; i++) {
        const int row = m0 + wm * 64 + i * 16 + r;
        #pragma unroll
        for (int j = 0; j < 4; j++) {
            const int col = n0 + wn * 32 + j * 8 + 2 * c;
            *(float2*)&C[(size_t)row * N + col] =
                make_float2(acc[i][j][0], acc[i][j][1]);
            *(float2*)&C[(size_t)(row + 8) * N + col] =
                make_float2(acc[i][j][2], acc[i][j][3]);
        }
    }
}

// ===========================================================================
// RoPE (in place on q, k segments of g_qkv)
// ===========================================================================
__global__ __launch_bounds__(1024) void rope_kernel(
    const float* __restrict__ sin_, const float* __restrict__ cos_)
{
    const int tok = blockIdx.x;
    const int t = tok & (Tt - 1);
    const int j = threadIdx.x;
    const int seg = j >> 9;
    const int p = j & 511;
    float* base = g_qkv + (size_t)tok * 3 * DIMc + seg * DIMc;
    const int d = p * 2;
    const int dh = d & (HDd - 1);
    const float c = cos_[t * HDd + dh];
    const float s = sin_[t * HDd + dh];
    float2 v = *(float2*)&base[d];
    float2 r = make_float2(v.x * c - v.y * s, v.y * c + v.x * s);
    *(float2*)&base[d] = r;
}

// ===========================================================================
// Flash attention, fp32, causal. BQ=BKV=64, 256 threads, 4x4 per thread.
// ===========================================================================
#define FLASH_SMEM ((3 * 64 * 64 + 3 * 64) * 4)

__global__ __launch_bounds__(256) void flash_kernel(float* __restrict__ Y)
{
    extern __shared__ float fsm[];
    float* Qs    = fsm;
    float* KS    = fsm + 4096;
    float* Vs    = fsm + 8192;
    float* row_m = fsm + 12288;
    float* row_l = row_m + 64;
    float* row_c = row_l + 64;

    const int qt = blockIdx.x;
    const int h  = blockIdx.y;
    const int b  = blockIdx.z;
    const int tid = threadIdx.x;
    const int tr = tid >> 4;
    const int tc = tid & 15;
    const int lrow = tid >> 2, llane = tid & 3;

    const int tok0 = b * Tt + qt * 64;
    const float* qbase = g_qkv + (size_t)tok0 * 3 * DIMc + h * HDd;

    #pragma unroll
    for (int cc = 0; cc < 4; cc++) {
        const int col = cc * 16 + llane * 4;
        float4 v = *(const float4*)(qbase + (size_t)lrow * 3 * DIMc + col);
        v.x *= 0.125f; v.y *= 0.125f; v.z *= 0.125f; v.w *= 0.125f;
        *(float4*)&Qs[lrow * 64 + col] = v;
    }
    if (tid < 64) { row_m[tid] = -INFINITY; row_l[tid] = 0.0f; }

    float o[4][4] = {};

    for (int kt = 0; kt <= qt; kt++) {
        const int ktok0 = b * Tt + kt * 64;
        const float* kbase = g_qkv + (size_t)ktok0 * 3 * DIMc + DIMc + h * HDd;
        const float* vbase = kbase + DIMc;

        __syncthreads();

        #pragma unroll
        for (int cc = 0; cc < 4; cc++) {
            const int col = cc * 16 + llane * 4;
            float4 kv4 = *(const float4*)(kbase + (size_t)lrow * 3 * DIMc + col);
            KS[(col + 0) * 64 + lrow] = kv4.x;
            KS[(col + 1) * 64 + lrow] = kv4.y;
            KS[(col + 2) * 64 + lrow] = kv4.z;
            KS[(col + 3) * 64 + lrow] = kv4.w;
            float4 vv = *(const float4*)(vbase + (size_t)lrow * 3 * DIMc + col);
            *(float4*)&Vs[lrow * 64 + col] = vv;
        }
        __syncthreads();

        float s_[4][4] = {};
        #pragma unroll
        for (int d0 = 0; d0 < 64; d0 += 4) {
            float a[4][4], bk[4][4];
            #pragma unroll
            for (int i = 0; i < 4; i++) {
                float4 t = *(const float4*)&Qs[(tr * 4 + i) * 64 + d0];
                a[i][0] = t.x; a[i][1] = t.y; a[i][2] = t.z; a[i][3] = t.w;
            }
            #pragma unroll
            for (int dd = 0; dd < 4; dd++) {
                float4 t = *(const float4*)&KS[(d0 + dd) * 64 + tc * 4];
                bk[dd][0] = t.x; bk[dd][1] = t.y; bk[dd][2] = t.z; bk[dd][3] = t.w;
            }
            #pragma unroll
            for (int i = 0; i < 4; i++)
                #pragma unroll
                for (int j = 0; j < 4; j++)
                    s_[i][j] += a[i][0] * bk[0][j] + a[i][1] * bk[1][j]
                              + a[i][2] * bk[2][j] + a[i][3] * bk[3][j];
        }

        if (kt == qt) {
            #pragma unroll
            for (int i = 0; i < 4; i++)
                #pragma unroll
                for (int j = 0; j < 4; j++)
                    if ((tc * 4 + j) > (tr * 4 + i)) s_[i][j] = -INFINITY;
        }

        __syncthreads();

        #pragma unroll
        for (int i = 0; i < 4; i++) {
            float4 st = make_float4(s_[i][0], s_[i][1], s_[i][2], s_[i][3]);
            *(float4*)&KS[(tr * 4 + i) * 64 + tc * 4] = st;
        }
        __syncthreads();

        {
            const int q = tid >> 2;
            const int quad = tid & 3;
            float* row = &KS[q * 64 + quad * 16];
            const float m_old = row_m[q];
            float4 v0 = *(float4*)(row + 0);
            float4 v1 = *(float4*)(row + 4);
            float4 v2 = *(float4*)(row + 8);
            float4 v3 = *(float4*)(row + 12);
            float mx = fmaxf(fmaxf(fmaxf(v0.x, v0.y), fmaxf(v0.z, v0.w)),
                             fmaxf(fmaxf(v1.x, v1.y), fmaxf(v1.z, v1.w)));
            mx = fmaxf(mx, fmaxf(fmaxf(fmaxf(v2.x, v2.y), fmaxf(v2.z, v2.w)),
                                 fmaxf(fmaxf(v3.x, v3.y), fmaxf(v3.z, v3.w))));
            mx = fmaxf(mx, __shfl_xor_sync(0xffffffffu, mx, 1));
            mx = fmaxf(mx, __shfl_xor_sync(0xffffffffu, mx, 2));
            mx = fmaxf(mx, m_old);
            v0.x = __expf(v0.x - mx); v0.y = __expf(v0.y - mx);
            v0.z = __expf(v0.z - mx); v0.w = __expf(v0.w - mx);
            v1.x = __expf(v1.x - mx); v1.y = __expf(v1.y - mx);
            v1.z = __expf(v1.z - mx); v1.w = __expf(v1.w - mx);
            v2.x = __expf(v2.x - mx); v2.y = __expf(v2.y - mx);
            v2.z = __expf(v2.z - mx); v2.w = __expf(v2.w - mx);
            v3.x = __expf(v3.x - mx); v3.y = __expf(v3.y - mx);
            v3.z = __expf(v3.z - mx); v3.w = __expf(v3.w - mx);
            float l = (v0.x + v0.y + v0.z + v0.w) + (v1.x + v1.y + v1.z + v1.w)
                    + (v2.x + v2.y + v2.z + v2.w) + (v3.x + v3.y + v3.z + v3.w);
            *(float4*)(row + 0)  = v0;
            *(float4*)(row + 4)  = v1;
            *(float4*)(row + 8)  = v2;
            *(float4*)(row + 12) = v3;
            l += __shfl_xor_sync(0xffffffffu, l, 1);
            l += __shfl_xor_sync(0xffffffffu, l, 2);
            if (quad == 0) {
                const float corr = __expf(m_old - mx);
                row_m[q] = mx;
                row_l[q] = row_l[q] * corr + l;
                row_c[q] = corr;
            }
        }
        __syncthreads();

        float ci[4];
        #pragma unroll
        for (int i = 0; i < 4; i++) ci[i] = row_c[tr * 4 + i];
        #pragma unroll
        for (int i = 0; i < 4; i++)
            #pragma unroll
            for (int j = 0; j < 4; j++) o[i][j] *= ci[i];

        #pragma unroll
        for (int kv0 = 0; kv0 < 64; kv0 += 4) {
            float p[4][4], v4[4][4];
            #pragma unroll
            for (int i = 0; i < 4; i++) {
                float4 t = *(const float4*)&KS[(tr * 4 + i) * 64 + kv0];
                p[i][0] = t.x; p[i][1] = t.y; p[i][2] = t.z; p[i][3] = t.w;
            }
            #pragma unroll
            for (int kk = 0; kk < 4; kk++) {
                float4 t = *(const float4*)&Vs[(kv0 + kk) * 64 + tc * 4];
                v4[kk][0] = t.x; v4[kk][1] = t.y; v4[kk][2] = t.z; v4[kk][3] = t.w;
            }
            #pragma unroll
            for (int i = 0; i < 4; i++)
                #pragma unroll
                for (int j = 0; j < 4; j++)
                    o[i][j] += p[i][0] * v4[0][j] + p[i][1] * v4[1][j]
                             + p[i][2] * v4[2][j] + p[i][3] * v4[3][j];
        }
    }

    #pragma unroll
    for (int i = 0; i < 4; i++) {
        const float li = 1.0f / row_l[tr * 4 + i];
        float4 st = make_float4(o[i][0] * li, o[i][1] * li, o[i][2] * li, o[i][3] * li);
        *(float4*)&Y[(size_t)(tok0 + tr * 4 + i) * DIMc + h * HDd + tc * 4] = st;
    }
}

// ===========================================================================
extern "C" void kernel_launch(void* const* d_in, const int* in_sizes, int n_in,
                              void* d_out, int out_size)
{
    const float* x      = (const float*)d_in[0];
    const float* sin_   = (const float*)d_in[1];
    const float* cos_   = (const float*)d_in[2];
    const float* W_qkv  = (const float*)d_in[3];
    const float* W_proj = (const float*)d_in[4];
    float* out = (float*)d_out;

    void *pqkv = nullptr, *py = nullptr, *pah = nullptr, *pal = nullptr;
    void *pwqh = nullptr, *pwql = nullptr, *pwph = nullptr, *pwpl = nullptr;
    cudaGetSymbolAddress(&pqkv, g_qkv);
    cudaGetSymbolAddress(&py, g_y);
    cudaGetSymbolAddress(&pah, g_ah);
    cudaGetSymbolAddress(&pal, g_al);
    cudaGetSymbolAddress(&pwqh, g_wqh);
    cudaGetSymbolAddress(&pwql, g_wql);
    cudaGetSymbolAddress(&pwph, g_wph);
    cudaGetSymbolAddress(&pwpl, g_wpl);

    cudaFuncSetAttribute(gemm_f16x3, cudaFuncAttributeMaxDynamicSharedMemorySize, GEMM_SMEM);
    cudaFuncSetAttribute(flash_kernel, cudaFuncAttributeMaxDynamicSharedMemorySize, FLASH_SMEM);

    const int nsplit = NTOK * DIMc / 8 / 256;   // 8 floats per thread

    // 0) Split weights (transposed) and x into fp16 hi/lo
    transpose_split<<<dim3(3 * DIMc / 32, DIMc / 32), dim3(32, 8)>>>(
        W_qkv, (__half*)pwqh, (__half*)pwql, DIMc, 3 * DIMc);
    transpose_split<<<dim3(DIMc / 32, DIMc / 32), dim3(32, 8)>>>(
        W_proj, (__half*)pwph, (__half*)pwpl, DIMc, DIMc);
    split_hi_lo<<<nsplit, 256>>>(x, (__half*)pah, (__half*)pal);

    // 1) QKV = x @ W_qkv  (3xFP16 mma k16)
    gemm_f16x3<<<dim3(3 * DIMc / 128, NTOK / 128), 256, GEMM_SMEM>>>(
        (const __half*)pah, (const __half*)pal, (const __half*)pwqh, (const __half*)pwql,
        (float*)pqkv, NTOK, 3 * DIMc, DIMc);

    // 2) RoPE on q, k
    rope_kernel<<<NTOK, 1024>>>(sin_, cos_);

    // 3) Causal flash attention -> g_y
    flash_kernel<<<dim3(Tt / 64, NHh, Bb), 256, FLASH_SMEM>>>((float*)py);

    // 4) Split y, then out = y @ W_proj
    split_hi_lo<<<nsplit, 256>>>((const float*)py, (__half*)pah, (__half*)pal);
    gemm_f16x3<<<dim3(DIMc / 128, NTOK / 128), 256, GEMM_SMEM>>>(
        (const __half*)pah, (const __half*)pal, (const __half*)pwph, (const __half*)pwpl,
        out, NTOK, DIMc, DIMc);
}

// round 17
// speedup vs baseline: 2.4418x; 1.5573x over previous
#include <cuda_runtime.h>
#include <cuda_fp16.h>
#include <math.h>
#include <stdint.h>

#define Bb   2
#define Tt   2048
#define DIMc 1024
#define NHh  16
#define HDd  64
#define NTOK (Bb*Tt)

// Scratch (device globals — no runtime allocation allowed)
__device__ float  g_qkv[(size_t)NTOK * 3 * DIMc];    // [tok][3*DIM] fp32 q|k|v (pre-rope)
__device__ float  g_y[(size_t)NTOK * DIMc];          // attention output fp32
__device__ __half g_qkvh[(size_t)NTOK * 3 * DIMc];   // rope'd qkv hi halves
__device__ __half g_qkvl[(size_t)NTOK * 3 * DIMc];   // rope'd qkv lo halves
__device__ __half g_ah[(size_t)NTOK * DIMc];         // activation hi (x, then y)
__device__ __half g_al[(size_t)NTOK * DIMc];         // activation lo
__device__ __half g_wqh[(size_t)3 * DIMc * DIMc];    // W_qkv^T hi [3*DIM][DIM]
__device__ __half g_wql[(size_t)3 * DIMc * DIMc];    // W_qkv^T lo
__device__ __half g_wph[(size_t)DIMc * DIMc];        // W_proj^T hi
__device__ __half g_wpl[(size_t)DIMc * DIMc];        // W_proj^T lo

// ===========================================================================
// Helpers
// ===========================================================================
__device__ __forceinline__ uint32_t smem_u32(const void* p) {
    uint32_t a;
    asm("{ .reg .u64 t; cvta.to.shared.u64 t, %1; cvt.u32.u64 %0, t; }" : "=r"(a) : "l"(p));
    return a;
}
__device__ __forceinline__ void cp_async16(uint32_t dst, const void* src) {
    asm volatile("cp.async.cg.shared.global [%0], [%1], 16;" :: "r"(dst), "l"(src));
}
#define CP_COMMIT()  asm volatile("cp.async.commit_group;")
#define CP_WAIT2()   asm volatile("cp.async.wait_group 2;" ::: "memory")
#define CP_WAIT1()   asm volatile("cp.async.wait_group 1;" ::: "memory")
#define CP_WAIT0()   asm volatile("cp.async.wait_group 0;" ::: "memory")

// fp16 mma k16: D(f32) = A(16x16 f16, row) * B(16x8 f16, col) + D
__device__ __forceinline__ void mma_f16(float* d, const uint32_t* a, const uint32_t* b) {
    asm volatile(
        "mma.sync.aligned.m16n8k16.row.col.f32.f16.f16.f32 "
        "{%0,%1,%2,%3}, {%4,%5,%6,%7}, {%8,%9}, {%0,%1,%2,%3};"
        : "+f"(d[0]), "+f"(d[1]), "+f"(d[2]), "+f"(d[3])
        : "r"(a[0]), "r"(a[1]), "r"(a[2]), "r"(a[3]), "r"(b[0]), "r"(b[1]));
}
__device__ __forceinline__ void ldsm_x4(uint32_t* r, uint32_t addr) {
    asm volatile("ldmatrix.sync.aligned.m8n8.x4.shared.b16 {%0,%1,%2,%3}, [%4];"
        : "=r"(r[0]), "=r"(r[1]), "=r"(r[2]), "=r"(r[3]) : "r"(addr));
}
__device__ __forceinline__ void ldsm_x4_t(uint32_t* r, uint32_t addr) {
    asm volatile("ldmatrix.sync.aligned.m8n8.x4.trans.shared.b16 {%0,%1,%2,%3}, [%4];"
        : "=r"(r[0]), "=r"(r[1]), "=r"(r[2]), "=r"(r[3]) : "r"(addr));
}
__device__ __forceinline__ uint32_t packh2(float lo, float hi) {
    __half2 h = __floats2half2_rn(lo, hi);
    return *(uint32_t*)&h;
}

// ===========================================================================
// Elementwise fp16 hi/lo split (activations): 8 floats -> 8+8 halfs per thread
// ===========================================================================
__global__ __launch_bounds__(256) void split_hi_lo(
    const float* __restrict__ X, __half* __restrict__ H, __half* __restrict__ L)
{
    const int i = blockIdx.x * 256 + threadIdx.x;
    const float4 v0 = ((const float4*)X)[2 * i];
    const float4 v1 = ((const float4*)X)[2 * i + 1];
    float v[8] = {v0.x, v0.y, v0.z, v0.w, v1.x, v1.y, v1.z, v1.w};
    __half h[8], l[8];
    #pragma unroll
    for (int j = 0; j < 8; j++) {
        h[j] = __float2half_rn(v[j]);
        l[j] = __float2half_rn(v[j] - __half2float(h[j]));
    }
    ((uint4*)H)[i] = *(uint4*)h;
    ((uint4*)L)[i] = *(uint4*)l;
}

// ===========================================================================
// Weight transpose + fp16 split
// ===========================================================================
__global__ __launch_bounds__(256) void transpose_split(
    const float* __restrict__ W, __half* __restrict__ Wh, __half* __restrict__ Wl,
    int K, int N)
{
    __shared__ float t[32][33];
    const int n0 = blockIdx.x * 32, k0 = blockIdx.y * 32;
    const int x = threadIdx.x, y = threadIdx.y;
    #pragma unroll
    for (int i = y; i < 32; i += 8)
        t[i][x] = W[(size_t)(k0 + i) * N + n0 + x];
    __syncthreads();
    #pragma unroll
    for (int i = y; i < 32; i += 8) {
        const float v = t[x][i];
        const __half h = __float2half_rn(v);
        Wh[(size_t)(n0 + i) * K + k0 + x] = h;
        Wl[(size_t)(n0 + i) * K + k0 + x] = __float2half_rn(v - __half2float(h));
    }
}

// ===========================================================================
// 3xFP16 GEMM (unchanged from R15, proven)
// ===========================================================================
#define GEMM_SMEM (3 * 32768)

__global__ __launch_bounds__(256, 2) void gemm_f16x3(
    const __half* __restrict__ Ah, const __half* __restrict__ Al,
    const __half* __restrict__ Bh, const __half* __restrict__ Bl,
    float* __restrict__ C, int M, int N, int K)
{
    extern __shared__ char sm[];
    const uint32_t smem_base = smem_u32(sm);

    const int tid  = threadIdx.x;
    const int lane = tid & 31;
    const int wid  = tid >> 5;
    const int wm   = wid >> 2;
    const int wn   = wid & 3;
    const int r    = lane >> 2;
    const int c    = lane & 3;
    const int lane8 = lane & 7, mat = lane >> 3;
    const int m0 = blockIdx.y * 128, n0 = blockIdx.x * 128;
    const int NK = K >> 5;

    const uint32_t a_lane_off = (uint32_t)((mat >> 1) * 2048 + (wm * 64 + (mat & 1) * 8 + lane8) * 16);
    const uint32_t b_lane_off = (uint32_t)((mat >> 1) * 2048 + (wn * 32 + (mat & 1) * 8 + lane8) * 16);

    float acc[4][4][4] = {};

    auto load_stage = [&](int kt, int s) {
        const int k0 = kt * 32;
        const uint32_t st = smem_base + (uint32_t)s * 32768;
        #pragma unroll
        for (int i = 0; i < 8; i++) {
            const int chunk = tid + i * 256;
            const int region = chunk >> 9;
            const int within = chunk & 511;
            const int row = within >> 2, kg = within & 3;
            const uint32_t dst = st + (uint32_t)(region * 8192 + kg * 2048 + row * 16);
            const __half* src;
            if      (region == 0) src = Ah + (size_t)(m0 + row) * K + k0 + kg * 8;
            else if (region == 1) src = Al + (size_t)(m0 + row) * K + k0 + kg * 8;
            else if (region == 2) src = Bh + (size_t)(n0 + row) * K + k0 + kg * 8;
            else                  src = Bl + (size_t)(n0 + row) * K + k0 + kg * 8;
            cp_async16(dst, src);
        }
    };

    load_stage(0, 0); CP_COMMIT();
    load_stage(1, 1); CP_COMMIT();

    for (int kt = 0; kt < NK; kt++) {
        const int s = kt - (kt / 3) * 3;
        if (kt + 2 < NK) {
            const int s2 = (kt + 2) - ((kt + 2) / 3) * 3;
            load_stage(kt + 2, s2);
            CP_COMMIT();
            CP_WAIT2();
        } else if (kt + 1 < NK) {
            CP_WAIT1();
        } else {
            CP_WAIT0();
        }
        __syncthreads();

        const uint32_t st = smem_base + (uint32_t)s * 32768;
        const uint32_t aBase = st + a_lane_off;
        const uint32_t bBase = st + 16384 + b_lane_off;

        #pragma unroll
        for (int s16 = 0; s16 < 2; s16++) {
            uint32_t ahi[4][4], alo[4][4], bhi[4][2], blo[4][2];
            #pragma unroll
            for (int i = 0; i < 4; i++) {
                ldsm_x4(ahi[i], aBase +        (uint32_t)(s16 * 4096 + i * 256));
                ldsm_x4(alo[i], aBase + 8192 + (uint32_t)(s16 * 4096 + i * 256));
            }
            #pragma unroll
            for (int jp = 0; jp < 2; jp++) {
                uint32_t th[4], tl[4];
                ldsm_x4(th, bBase +        (uint32_t)(s16 * 4096 + jp * 256));
                ldsm_x4(tl, bBase + 8192 + (uint32_t)(s16 * 4096 + jp * 256));
                bhi[2 * jp][0] = th[0]; bhi[2 * jp + 1][0] = th[1];
                bhi[2 * jp][1] = th[2]; bhi[2 * jp + 1][1] = th[3];
                blo[2 * jp][0] = tl[0]; blo[2 * jp + 1][0] = tl[1];
                blo[2 * jp][1] = tl[2]; blo[2 * jp + 1][1] = tl[3];
            }
            #pragma unroll
            for (int i = 0; i < 4; i++)
                #pragma unroll
                for (int j = 0; j < 4; j++) {
                    mma_f16(acc[i][j], alo[i], bhi[j]);
                    mma_f16(acc[i][j], ahi[i], blo[j]);
                    mma_f16(acc[i][j], ahi[i], bhi[j]);
                }
        }
        __syncthreads();
    }

    #pragma unroll
    for (int i = 0; i < 4; i++) {
        const int row = m0 + wm * 64 + i * 16 + r;
        #pragma unroll
        for (int j = 0; j < 4; j++) {
            const int col = n0 + wn * 32 + j * 8 + 2 * c;
            *(float2*)&C[(size_t)row * N + col] =
                make_float2(acc[i][j][0], acc[i][j][1]);
            *(float2*)&C[(size_t)(row + 8) * N + col] =
                make_float2(acc[i][j][2], acc[i][j][3]);
        }
    }
}

// ===========================================================================
// Fused RoPE + hi/lo split: g_qkv (fp32) -> g_qkvh/g_qkvl (halfs).
// q gets rope * 0.125 (attention scale folded in); k gets rope; v passthrough.
// ===========================================================================
__global__ __launch_bounds__(256) void rope_split(
    const float* __restrict__ sin_, const float* __restrict__ cos_)
{
    const int tok = blockIdx.x;
    const int t = tok & (Tt - 1);
    const float* base = g_qkv + (size_t)tok * 3 * DIMc;
    #pragma unroll
    for (int i = 0; i < 3; i++) {
        const int j4 = (i * 256 + threadIdx.x) * 4;   // 4-elem group
        float4 v = *(const float4*)(base + j4);
        const int seg = j4 >> 10;                      // 0=q 1=k 2=v
        if (seg < 2) {
            const int dh = j4 & (HDd - 1);
            const float c0 = cos_[t * HDd + dh],     s0 = sin_[t * HDd + dh];
            const float c1 = cos_[t * HDd + dh + 2], s1 = sin_[t * HDd + dh + 2];
            float r0 = v.x * c0 - v.y * s0;
            float r1 = v.y * c0 + v.x * s0;
            float r2 = v.z * c1 - v.w * s1;
            float r3 = v.w * c1 + v.z * s1;
            if (seg == 0) { r0 *= 0.125f; r1 *= 0.125f; r2 *= 0.125f; r3 *= 0.125f; }
            v = make_float4(r0, r1, r2, r3);
        }
        float a[4] = {v.x, v.y, v.z, v.w};
        __half h[4], l[4];
        #pragma unroll
        for (int j = 0; j < 4; j++) {
            h[j] = __float2half_rn(a[j]);
            l[j] = __float2half_rn(a[j] - __half2float(h[j]));
        }
        *(uint2*)(g_qkvh + (size_t)tok * 3 * DIMc + j4) = *(uint2*)h;
        *(uint2*)(g_qkvl + (size_t)tok * 3 * DIMc + j4) = *(uint2*)l;
    }
}

// ===========================================================================
// Tensor-core flash attention, causal. BQ=128, BKV=64, 8 warps x 16 q-rows.
// S = Q K^T via 3xFP16 (hi/lo); softmax in registers (rows on 4 lanes);
// P packed from S accs (single fp16), O += P*Vh + P*Vl (V exact).
// Smem: Q resident [Qh 16K|Ql 16K] + 2 KV stages [Kh 8K|Kl 8K|Vh 8K|Vl 8K].
//   All operands in k8-slab layout: [slab dg][row][8 halfs] (16B rows).
// ===========================================================================
#define FLASH_SMEM (32768 + 2 * 32768)

__global__ __launch_bounds__(256, 2) void flash_mma(float* __restrict__ Y)
{
    extern __shared__ char sm[];
    const uint32_t smb = smem_u32(sm);

    const int tid  = threadIdx.x;
    const int lane = tid & 31;
    const int wq   = tid >> 5;            // warp's 16-row slab (0..7)
    const int qr   = lane >> 2;           // 0..7
    const int c2   = (lane & 3) * 2;      // acc col pair base
    const int lane8 = lane & 7, mat = lane >> 3;

    const int qt = blockIdx.x;            // q tile (16)
    const int h  = blockIdx.y;            // head
    const int b  = blockIdx.z;            // batch
    const int t0q = qt * 128;             // local q row base
    const size_t tokb = (size_t)b * Tt;

    // ldsm lane bases
    const uint32_t qa_lane = (uint32_t)((mat >> 1) * 2048 + (wq * 16 + (mat & 1) * 8 + lane8) * 16);
    const uint32_t kv_lane = (uint32_t)((mat >> 1) * 1024 + ((mat & 1) * 8 + lane8) * 16);

    // ---- Q load (2048 chunks; resident for whole CTA) ----
    #pragma unroll
    for (int i = 0; i < 8; i++) {
        const int chunk = tid + i * 256;
        const int prec = chunk >> 10;              // 0=hi 1=lo
        const int within = chunk & 1023;
        const int row = within >> 3, dg = within & 7;
        const __half* src = (prec ? g_qkvl : g_qkvh)
            + (tokb + t0q + row) * (3 * DIMc) + h * HDd + dg * 8;
        cp_async16(smb + (uint32_t)(prec * 16384 + dg * 2048 + row * 16), src);
    }

    auto load_kv = [&](int kt, int s) {
        const int k0 = kt * 64;
        const uint32_t st = smb + 32768 + (uint32_t)s * 32768;
        #pragma unroll
        for (int i = 0; i < 8; i++) {
            const int chunk = tid + i * 256;
            const int region = chunk >> 9;         // 0:Kh 1:Kl 2:Vh 3:Vl
            const int within = chunk & 511;
            const int row = within >> 3, dg = within & 7;
            const int goff = (region >> 1) ? 2 * DIMc : DIMc;   // v : k
            const __half* src = ((region & 1) ? g_qkvl : g_qkvh)
                + (tokb + k0 + row) * (3 * DIMc) + goff + h * HDd + dg * 8;
            cp_async16(st + (uint32_t)(region * 8192 + dg * 1024 + row * 16), src);
        }
    };

    load_kv(0, 0);
    CP_COMMIT();

    float oacc[8][4] = {};
    float m_a = -INFINITY, m_b = -INFINITY, l_a = 0.0f, l_b = 0.0f;
    const int rowa = t0q + wq * 16 + qr;
    const int rowb = rowa + 8;

    const int NT = 2 * qt + 2;
    for (int kt = 0; kt < NT; kt++) {
        const int s = kt & 1;
        CP_WAIT0();
        __syncthreads();
        if (kt + 1 < NT) { load_kv(kt + 1, s ^ 1); CP_COMMIT(); }

        const uint32_t kst = smb + 32768 + (uint32_t)s * 32768;
        const uint32_t qa = smb + qa_lane;
        const uint32_t kb = kst + kv_lane;            // Kh region
        const uint32_t vb = kst + 16384 + kv_lane;    // Vh region

        // ---- S = Q K^T (3xFP16) ----
        float sacc[8][4] = {};
        #pragma unroll
        for (int t = 0; t < 4; t++) {                 // k16 over d
            uint32_t qh[4], ql[4];
            ldsm_x4(qh, qa + (uint32_t)(t * 4096));
            ldsm_x4(ql, qa + 16384 + (uint32_t)(t * 4096));
            #pragma unroll
            for (int jn = 0; jn < 4; jn++) {          // n16 over kv
                uint32_t kh[4], kl[4];
                ldsm_x4(kh, kb + (uint32_t)(t * 2048 + jn * 256));
                ldsm_x4(kl, kb + 8192 + (uint32_t)(t * 2048 + jn * 256));
                uint32_t beh[2] = {kh[0], kh[2]}, boh[2] = {kh[1], kh[3]};
                uint32_t bel[2] = {kl[0], kl[2]}, bol[2] = {kl[1], kl[3]};
                mma_f16(sacc[2 * jn],     ql, beh);
                mma_f16(sacc[2 * jn],     qh, bel);
                mma_f16(sacc[2 * jn],     qh, beh);
                mma_f16(sacc[2 * jn + 1], ql, boh);
                mma_f16(sacc[2 * jn + 1], qh, bol);
                mma_f16(sacc[2 * jn + 1], qh, boh);
            }
        }

        // ---- causal mask (last two tiles only) ----
        if (kt >= 2 * qt) {
            const int colb = kt * 64 + c2;
            #pragma unroll
            for (int jt = 0; jt < 8; jt++) {
                const int col = colb + jt * 8;
                if (col > rowa)     sacc[jt][0] = -INFINITY;
                if (col + 1 > rowa) sacc[jt][1] = -INFINITY;
                if (col > rowb)     sacc[jt][2] = -INFINITY;
                if (col + 1 > rowb) sacc[jt][3] = -INFINITY;
            }
        }

        // ---- online softmax in registers ----
        float mxa = m_a, mxb = m_b;
        #pragma unroll
        for (int jt = 0; jt < 8; jt++) {
            mxa = fmaxf(mxa, fmaxf(sacc[jt][0], sacc[jt][1]));
            mxb = fmaxf(mxb, fmaxf(sacc[jt][2], sacc[jt][3]));
        }
        mxa = fmaxf(mxa, __shfl_xor_sync(0xffffffffu, mxa, 1));
        mxa = fmaxf(mxa, __shfl_xor_sync(0xffffffffu, mxa, 2));
        mxb = fmaxf(mxb, __shfl_xor_sync(0xffffffffu, mxb, 1));
        mxb = fmaxf(mxb, __shfl_xor_sync(0xffffffffu, mxb, 2));
        const float corra = __expf(m_a - mxa);
        const float corrb = __expf(m_b - mxb);
        m_a = mxa; m_b = mxb;

        float suma = 0.0f, sumb = 0.0f;
        #pragma unroll
        for (int jt = 0; jt < 8; jt++) {
            sacc[jt][0] = __expf(sacc[jt][0] - mxa);
            sacc[jt][1] = __expf(sacc[jt][1] - mxa);
            sacc[jt][2] = __expf(sacc[jt][2] - mxb);
            sacc[jt][3] = __expf(sacc[jt][3] - mxb);
            suma += sacc[jt][0] + sacc[jt][1];
            sumb += sacc[jt][2] + sacc[jt][3];
        }
        suma += __shfl_xor_sync(0xffffffffu, suma, 1);
        suma += __shfl_xor_sync(0xffffffffu, suma, 2);
        sumb += __shfl_xor_sync(0xffffffffu, sumb, 1);
        sumb += __shfl_xor_sync(0xffffffffu, sumb, 2);
        l_a = l_a * corra + suma;
        l_b = l_b * corrb + sumb;

        #pragma unroll
        for (int jt = 0; jt < 8; jt++) {
            oacc[jt][0] *= corra; oacc[jt][1] *= corra;
            oacc[jt][2] *= corrb; oacc[jt][3] *= corrb;
        }

        // ---- pack P into A fragments (fp16) ----
        uint32_t pk[4][4];
        #pragma unroll
        for (int t = 0; t < 4; t++) {
            pk[t][0] = packh2(sacc[2 * t][0],     sacc[2 * t][1]);
            pk[t][1] = packh2(sacc[2 * t][2],     sacc[2 * t][3]);
            pk[t][2] = packh2(sacc[2 * t + 1][0], sacc[2 * t + 1][1]);
            pk[t][3] = packh2(sacc[2 * t + 1][2], sacc[2 * t + 1][3]);
        }

        // ---- O += P * V  (V exact via hi+lo) ----
        #pragma unroll
        for (int t = 0; t < 4; t++) {                 // k16 over kv
            #pragma unroll
            for (int g = 0; g < 4; g++) {             // d16 group
                uint32_t vh[4], vl[4];
                ldsm_x4_t(vh, vb + (uint32_t)(g * 2048 + t * 256));
                ldsm_x4_t(vl, vb + 8192 + (uint32_t)(g * 2048 + t * 256));
                mma_f16(oacc[2 * g],     pk[t], vh);
                mma_f16(oacc[2 * g],     pk[t], vl);
                mma_f16(oacc[2 * g + 1], pk[t], vh + 2);
                mma_f16(oacc[2 * g + 1], pk[t], vl + 2);
            }
        }
    }

    // ---- epilogue ----
    const float ila = 1.0f / l_a, ilb = 1.0f / l_b;
    float* ya = Y + (tokb + rowa) * DIMc + h * HDd;
    float* yb = Y + (tokb + rowb) * DIMc + h * HDd;
    #pragma unroll
    for (int jt = 0; jt < 8; jt++) {
        const int col = jt * 8 + c2;
        *(float2*)&ya[col] = make_float2(oacc[jt][0] * ila, oacc[jt][1] * ila);
        *(float2*)&yb[col] = make_float2(oacc[jt][2] * ilb, oacc[jt][3] * ilb);
    }
}

// ===========================================================================
extern "C" void kernel_launch(void* const* d_in, const int* in_sizes, int n_in,
                              void* d_out, int out_size)
{
    const float* x      = (const float*)d_in[0];
    const float* sin_   = (const float*)d_in[1];
    const float* cos_   = (const float*)d_in[2];
    const float* W_qkv  = (const float*)d_in[3];
    const float* W_proj = (const float*)d_in[4];
    float* out = (float*)d_out;

    void *pqkv = nullptr, *py = nullptr, *pah = nullptr, *pal = nullptr;
    void *pwqh = nullptr, *pwql = nullptr, *pwph = nullptr, *pwpl = nullptr;
    cudaGetSymbolAddress(&pqkv, g_qkv);
    cudaGetSymbolAddress(&py, g_y);
    cudaGetSymbolAddress(&pah, g_ah);
    cudaGetSymbolAddress(&pal, g_al);
    cudaGetSymbolAddress(&pwqh, g_wqh);
    cudaGetSymbolAddress(&pwql, g_wql);
    cudaGetSymbolAddress(&pwph, g_wph);
    cudaGetSymbolAddress(&pwpl, g_wpl);

    cudaFuncSetAttribute(gemm_f16x3, cudaFuncAttributeMaxDynamicSharedMemorySize, GEMM_SMEM);
    cudaFuncSetAttribute(flash_mma, cudaFuncAttributeMaxDynamicSharedMemorySize, FLASH_SMEM);

    const int nsplit = NTOK * DIMc / 8 / 256;

    // 0) Split weights (transposed) and x into fp16 hi/lo
    transpose_split<<<dim3(3 * DIMc / 32, DIMc / 32), dim3(32, 8)>>>(
        W_qkv, (__half*)pwqh, (__half*)pwql, DIMc, 3 * DIMc);
    transpose_split<<<dim3(DIMc / 32, DIMc / 32), dim3(32, 8)>>>(
        W_proj, (__half*)pwph, (__half*)pwpl, DIMc, DIMc);
    split_hi_lo<<<nsplit, 256>>>(x, (__half*)pah, (__half*)pal);

    // 1) QKV = x @ W_qkv  (3xFP16 mma)
    gemm_f16x3<<<dim3(3 * DIMc / 128, NTOK / 128), 256, GEMM_SMEM>>>(
        (const __half*)pah, (const __half*)pal, (const __half*)pwqh, (const __half*)pwql,
        (float*)pqkv, NTOK, 3 * DIMc, DIMc);

    // 2) Fused RoPE + hi/lo split -> g_qkvh/g_qkvl
    rope_split<<<NTOK, 256>>>(sin_, cos_);

    // 3) Tensor-core causal flash attention -> g_y
    flash_mma<<<dim3(Tt / 128, NHh, Bb), 256, FLASH_SMEM>>>((float*)py);

    // 4) Split y, then out = y @ W_proj
    split_hi_lo<<<nsplit, 256>>>((const float*)py, (__half*)pah, (__half*)pal);
    gemm_f16x3<<<dim3(DIMc / 128, NTOK / 128), 256, GEMM_SMEM>>>(
        (const __half*)pah, (const __half*)pal, (const __half*)pwph, (const __half*)pwpl,
        out, NTOK, DIMc, DIMc);
}